// round 1
// baseline (speedup 1.0000x reference)
#include <cuda_runtime.h>

// DTL loss: inputs [M,N] f32, targets [M] i32 -> scalar f32
//   pos = inputs[r, tgt[r]]
//   hard = top-100 of row with target masked to -inf
//   out = mean_r( (1-pos)^2 + 0.2 * mean((1+hard)^2) )
//
// One CTA per row. Row lives in registers (20 keys/thread x 512 threads).
// Exact top-k via radix select on monotone uint keys + final rank select.

#define THREADS 512
#define PER_TH  20          // ceil(10001/512); supports n <= 10240
#define DELTA   0.2f

__device__ double g_sum;

__device__ __forceinline__ unsigned f2key(unsigned u) {
    // monotone: larger float -> larger key
    return u ^ (((unsigned)((int)u >> 31)) | 0x80000000u);
}
__device__ __forceinline__ float key2f(unsigned k) {
    unsigned u = (k & 0x80000000u) ? (k ^ 0x80000000u) : ~k;
    return __uint_as_float(u);
}

__global__ void zero_kernel() { g_sum = 0.0; }

__global__ void finalize_kernel(float* out, int m) {
    out[0] = (float)(g_sum / (double)m);
}

__global__ void __launch_bounds__(THREADS, 2) dtl_kernel(
    const float* __restrict__ inputs,
    const int*   __restrict__ targets,
    int n, int num_hard)
{
    __shared__ unsigned cand[THREADS * PER_TH];   // candidate keys (worst case whole row)
    __shared__ unsigned hist[32];
    __shared__ int   s_count;   // candidate count
    __shared__ int   s_sel;     // selected digit
    __shared__ int   s_k;       // remaining k within candidates
    __shared__ float s_pos;
    __shared__ float warp_sums[THREADS / 32];

    const int row  = blockIdx.x;
    const int tid  = threadIdx.x;
    const int lane = tid & 31;
    const int wid  = tid >> 5;
    const float* rowp = inputs + (size_t)row * (size_t)n;
    const int tgt = targets[row];

    if (tid < 32) hist[tid] = 0u;

    // ---------- Pass 1: load row into registers, packed 8-bin histogram of top 3 key bits
    unsigned keys[PER_TH];
    unsigned long long cnt = 0ull;   // 8 bins x 8-bit counters (counts <= 20 per thread)
#pragma unroll
    for (int i = 0; i < PER_TH; i++) {
        int col = tid + i * THREADS;
        unsigned key = 0u;           // out-of-range & masked-target -> key 0 (minimum)
        if (col < n) {
            float x = __ldg(rowp + col);
            unsigned u = __float_as_uint(x);
            key = f2key(u);
            if (col == tgt) { s_pos = x; key = 0u; }
        }
        keys[i] = key;
        cnt += 1ull << ((key >> 29) * 8u);
    }
    __syncthreads();                  // hist zero + s_pos visible ordering for later

    // reduce packed counters into shared hist (warp redux + 1 atomic per warp per bin)
#pragma unroll
    for (int b = 0; b < 8; b++) {
        unsigned v = (unsigned)((cnt >> (b * 8)) & 0xFFull);
        unsigned ws = __reduce_add_sync(0xffffffffu, v);
        if (lane == 0) atomicAdd(&hist[b], ws);
    }
    __syncthreads();

    // ---------- Scan 8 bins (warp 0): find boundary bin for k = num_hard
    if (wid == 0) {
        int k = num_hard;
        unsigned c = (lane < 8) ? hist[lane] : 0u;
        if (lane == 0) c -= (unsigned)(THREADS * PER_TH - n);   // remove fake key-0 pads
        unsigned s = c;
#pragma unroll
        for (int off = 1; off < 8; off <<= 1) {
            unsigned t = __shfl_down_sync(0xffffffffu, s, off);
            if (lane + off < 8) s += t;
        }
        unsigned above = s - c;       // strictly-higher-bin count
        bool cond = (lane < 8) && (above < (unsigned)k) && ((unsigned)k <= s);
        if (cond) { s_sel = lane; s_k = k - (int)above; }
        if (lane == 0) s_count = 0;
    }
    __syncthreads();

    // ---------- Pass 2 (registers): sum definite winners, compact boundary bin to smem
    float acc = 0.0f;
    {
        const unsigned sel = (unsigned)s_sel;
#pragma unroll
        for (int i = 0; i < PER_TH; i++) {
            unsigned key = keys[i];
            unsigned d = key >> 29;
            bool valid = (tid + i * THREADS) < n;
            if (d > sel) {                       // key 0 pads have d==0, never > sel
                float x = key2f(key);
                float t = 1.0f + x;
                acc = fmaf(t, t, acc);
            }
            bool eq = valid && (d == sel);
            unsigned emask = __ballot_sync(0xffffffffu, eq);
            if (emask) {
                int leader = __ffs(emask) - 1;
                int base = 0;
                if (lane == leader) base = atomicAdd(&s_count, __popc(emask));
                base = __shfl_sync(0xffffffffu, base, leader);
                if (eq) cand[base + __popc(emask & ((1u << lane) - 1u))] = key;
            }
        }
    }
    __syncthreads();

    // ---------- Fallback 5-bit radix passes while candidate set is large
    {
        const int shifts[6] = {24, 19, 14, 9, 4, 0};
        for (int pi = 0; pi < 6; pi++) {
            int c = s_count;
            if (c <= 64) break;                   // uniform decision
            int shift = shifts[pi];
            if (tid < 32) hist[tid] = 0u;
            __syncthreads();

            unsigned fb[PER_TH];                  // rare path; may live in local mem
            int nb = 0;
            for (int base = 0; base < c; base += THREADS) {
                int j = base + tid;
                unsigned key = 0u;
                if (j < c) {
                    key = cand[j];
                    atomicAdd(&hist[(key >> shift) & 31u], 1u);
                }
                fb[nb++] = key;
            }
            __syncthreads();

            if (wid == 0) {
                int kk = s_k;
                unsigned cc = hist[lane];
                unsigned s = cc;
#pragma unroll
                for (int off = 1; off < 32; off <<= 1) {
                    unsigned t = __shfl_down_sync(0xffffffffu, s, off);
                    if (lane + off < 32) s += t;
                }
                unsigned above = s - cc;
                bool cond = (above < (unsigned)kk) && ((unsigned)kk <= s);
                if (cond) { s_sel = lane; s_k = kk - (int)above; }
                if (lane == 0) s_count = 0;
            }
            __syncthreads();

            const unsigned sel = (unsigned)s_sel;
            int nb2 = 0;
            for (int base = 0; base < c; base += THREADS) {
                int j = base + tid;
                unsigned key = fb[nb2++];
                bool in = j < c;
                unsigned d = (key >> shift) & 31u;
                if (in && d > sel) {
                    float x = key2f(key);
                    float t = 1.0f + x;
                    acc = fmaf(t, t, acc);
                }
                bool eq = in && (d == sel);
                unsigned emask = __ballot_sync(0xffffffffu, eq);
                if (emask) {
                    int leader = __ffs(emask) - 1;
                    int b2 = 0;
                    if (lane == leader) b2 = atomicAdd(&s_count, __popc(emask));
                    b2 = __shfl_sync(0xffffffffu, b2, leader);
                    if (eq) cand[b2 + __popc(emask & ((1u << lane) - 1u))] = key;
                }
            }
            __syncthreads();
        }
    }

    // ---------- Exact rank select on the small candidate set (index tie-break)
    {
        int c = s_count;
        int k = s_k;
        for (int j = tid; j < c; j += THREADS) {
            unsigned mk = cand[j];
            int rank = 0;
            for (int t = 0; t < c; t++) {
                unsigned o = cand[t];
                rank += (o > mk) || (o == mk && t < j);
            }
            if (rank < k) {
                float x = key2f(mk);
                float tt = 1.0f + x;
                acc = fmaf(tt, tt, acc);
            }
        }
    }

    // ---------- Block reduction + per-row result
#pragma unroll
    for (int off = 16; off > 0; off >>= 1)
        acc += __shfl_down_sync(0xffffffffu, acc, off);
    if (lane == 0) warp_sums[wid] = acc;
    __syncthreads();
    if (tid == 0) {
        float tot = 0.0f;
#pragma unroll
        for (int w = 0; w < THREADS / 32; w++) tot += warp_sums[w];
        float pos = s_pos;
        float d1 = 1.0f - pos;
        float per_row = d1 * d1 + DELTA * (tot / (float)num_hard);
        atomicAdd(&g_sum, (double)per_row);
    }
}

extern "C" void kernel_launch(void* const* d_in, const int* in_sizes, int n_in,
                              void* d_out, int out_size) {
    const float* inputs  = (const float*)d_in[0];
    const int*   targets = (const int*)d_in[1];
    int m = in_sizes[1];                 // 4096 rows (targets count)
    int n = in_sizes[0] / m;             // 10001 cols
    int num_hard = (int)(0.01 * (double)(n - 1));   // matches int(R*(n-1)) = 100

    zero_kernel<<<1, 1>>>();
    dtl_kernel<<<m, THREADS>>>(inputs, targets, n, num_hard);
    finalize_kernel<<<1, 1>>>((float*)d_out, m);
}

// round 2
// speedup vs baseline: 1.7686x; 1.7686x over previous
#include <cuda_runtime.h>

// DTL loss: inputs [M,N] f32, targets [M] i32 -> scalar f32
//   pos = inputs[r, tgt[r]]
//   hard = top-num_hard of row with target masked to -inf
//   out = mean_r( (1-pos)^2 + 0.2 * mean((1+hard)^2) )
//
// One CTA per row. Row keys live in SHARED memory (no register arrays -> no
// spills). Exact top-k via 8-bin radix scan + candidate compaction + rank
// select. Bit-refinement fallback keeps exactness for degenerate rows.

#define THREADS 256
#define NMAX    10240      // supports n <= 10240 (bench n = 10001)
#define CAP     1024       // candidate buffer (expected ~228 for N(0,1))
#define DELTA   0.2f

__device__ double g_sum;

__device__ __forceinline__ unsigned f2key(unsigned u) {
    // monotone map: larger float -> larger unsigned key
    return u ^ (((unsigned)((int)u >> 31)) | 0x80000000u);
}
__device__ __forceinline__ float key2f(unsigned k) {
    unsigned u = (k & 0x80000000u) ? (k ^ 0x80000000u) : ~k;
    return __uint_as_float(u);
}

__global__ void zero_kernel() { g_sum = 0.0; }

__global__ void finalize_kernel(float* out, int m) {
    out[0] = (float)(g_sum / (double)m);
}

__global__ void __launch_bounds__(THREADS, 4) dtl_kernel(
    const float* __restrict__ inputs,
    const int*   __restrict__ targets,
    int n, int num_hard)
{
    __shared__ __align__(16) unsigned skeys[NMAX];
    __shared__ unsigned cand[CAP];
    __shared__ unsigned hist[32];
    __shared__ int   s_count, s_sel, s_k;
    __shared__ float s_pos;
    __shared__ float warp_sums[THREADS / 32];

    const int row  = blockIdx.x;
    const int tid  = threadIdx.x;
    const int lane = tid & 31;
    const int wid  = tid >> 5;
    const float* rowp = inputs + (size_t)row * (size_t)n;
    const int tgt = targets[row];

    if (tid < 32) hist[tid] = 0u;
    if (tid == 0) s_count = 0;

    // ---------- Pass 1: stream row DRAM->smem keys, packed 8-bin histogram of
    // the top 3 key bits. Target is masked to key 0 (below everything real)
    // and excluded from the histogram.
    unsigned long long cnt = 0ull;   // 8 bins x 8-bit counters (<= 40 each)
    for (int col = tid; col < n; col += THREADS) {
        float x = __ldg(rowp + col);
        unsigned key = f2key(__float_as_uint(x));
        bool is_t = (col == tgt);
        if (is_t) { s_pos = x; key = 0u; }
        skeys[col] = key;
        if (!is_t) cnt += 1ull << ((key >> 29) * 8u);
    }
    const int nv = (n + 3) & ~3;     // pad to uint4 multiple with key 0
    for (int j = n + tid; j < nv; j += THREADS) skeys[j] = 0u;
    __syncthreads();

    // reduce packed counters into shared hist (warp redux + 1 atomic/warp/bin)
#pragma unroll
    for (int b = 0; b < 8; b++) {
        unsigned v  = (unsigned)((cnt >> (b * 8)) & 0xFFull);
        unsigned ws = __reduce_add_sync(0xffffffffu, v);
        if (lane == 0 && ws) atomicAdd(&hist[b], ws);
    }
    __syncthreads();

    // ---------- Select boundary bin (warp 0 suffix-scan over 8 bins)
    if (wid == 0) {
        unsigned c = (lane < 8) ? hist[lane] : 0u;
        unsigned s = c;
#pragma unroll
        for (int off = 1; off < 8; off <<= 1) {
            unsigned t = __shfl_down_sync(0xffffffffu, s, off);
            if (lane + off < 8) s += t;
        }
        unsigned above = s - c;       // count in strictly higher bins
        if (lane < 8 && above < (unsigned)num_hard && (unsigned)num_hard <= s) {
            s_sel = (int)lane;
            s_k   = num_hard - (int)above;
        }
    }
    __syncthreads();

    // ---------- Pass 2: smem scan (LDS.128). Sum definite winners, compact
    // boundary bin. key==0 filter drops both pads and the masked target.
    float acc = 0.0f;
    const unsigned sel = (unsigned)s_sel;
    const int nv4 = nv >> 2;
    for (int j = tid; j < nv4; j += THREADS) {
        uint4 k4 = reinterpret_cast<const uint4*>(skeys)[j];
        unsigned ks[4] = {k4.x, k4.y, k4.z, k4.w};
#pragma unroll
        for (int s2 = 0; s2 < 4; s2++) {
            unsigned key = ks[s2];
            unsigned d = key >> 29;
            if (d > sel) {
                float t = 1.0f + key2f(key);
                acc = fmaf(t, t, acc);
            } else if (d == sel && key != 0u) {
                int p = atomicAdd(&s_count, 1);
                if (p < CAP) cand[p] = key;
            }
        }
    }
    __syncthreads();

    const int c = s_count;
    if (c <= CAP) {
        // ---------- Exact rank select (ties by array index; tied values are
        // equal, so the sum is identical to jax top_k's choice).
        const int k = s_k;
        for (int j = tid; j < c; j += THREADS) {
            unsigned mk = cand[j];
            int r = 0;
            for (int t = 0; t < c; t++) {
                unsigned o = cand[t];
                r += (o > mk) || (o == mk && t < j);
            }
            if (r < k) {
                float t = 1.0f + key2f(mk);
                acc = fmaf(t, t, acc);
            }
        }
    } else {
        // ---------- Exact fallback (pathological rows only): refine the key
        // prefix 5 bits at a time directly over smem keys.
        unsigned pmask = 0xE0000000u;
        unsigned pval  = sel << 29;
        const int shifts[6] = {24, 19, 14, 9, 4, 0};
        for (int lv = 0; lv < 6; lv++) {
            const int sh = shifts[lv];
            const unsigned wmask = (lv == 5) ? 0xFu : 0x1Fu;
            if (tid < 32) hist[tid] = 0u;
            __syncthreads();
            for (int col = tid; col < n; col += THREADS) {
                unsigned key = skeys[col];
                if (key != 0u && (key & pmask) == pval)
                    atomicAdd(&hist[(key >> sh) & wmask], 1u);
            }
            __syncthreads();
            if (wid == 0) {
                int kk = s_k;
                unsigned cc = hist[lane];
                unsigned s = cc;
#pragma unroll
                for (int off = 1; off < 32; off <<= 1) {
                    unsigned t = __shfl_down_sync(0xffffffffu, s, off);
                    if (lane + off < 32) s += t;
                }
                unsigned above = s - cc;
                if (above < (unsigned)kk && (unsigned)kk <= s) {
                    s_sel = (int)lane;
                    s_k   = kk - (int)above;
                }
            }
            __syncthreads();
            const unsigned dsel = (unsigned)s_sel;
            for (int col = tid; col < n; col += THREADS) {
                unsigned key = skeys[col];
                if (key != 0u && (key & pmask) == pval &&
                    ((key >> sh) & wmask) > dsel) {
                    float t = 1.0f + key2f(key);
                    acc = fmaf(t, t, acc);
                }
            }
            pval  |= dsel << sh;
            pmask |= wmask << sh;
            __syncthreads();
        }
        // remaining s_k elements are exactly equal to pval
        if (tid == 0) {
            float t = 1.0f + key2f(pval);
            acc = fmaf((float)s_k * t, t, acc);
        }
    }

    // ---------- Block reduction + per-row contribution
#pragma unroll
    for (int off = 16; off > 0; off >>= 1)
        acc += __shfl_down_sync(0xffffffffu, acc, off);
    if (lane == 0) warp_sums[wid] = acc;
    __syncthreads();
    if (tid == 0) {
        float tot = 0.0f;
#pragma unroll
        for (int w = 0; w < THREADS / 32; w++) tot += warp_sums[w];
        float d1 = 1.0f - s_pos;
        float hard = (num_hard > 0) ? tot / (float)num_hard : 0.0f;
        float per_row = d1 * d1 + DELTA * hard;
        atomicAdd(&g_sum, (double)per_row);
    }
}

extern "C" void kernel_launch(void* const* d_in, const int* in_sizes, int n_in,
                              void* d_out, int out_size) {
    const float* inputs  = (const float*)d_in[0];
    const int*   targets = (const int*)d_in[1];
    int m = in_sizes[1];                   // rows (targets count)
    int n = in_sizes[0] / m;               // cols
    int num_hard = (int)(0.01 * (double)(n - 1));   // int(R*(n-1))

    zero_kernel<<<1, 1>>>();
    dtl_kernel<<<m, THREADS>>>(inputs, targets, n, num_hard);
    finalize_kernel<<<1, 1>>>((float*)d_out, m);
}